// round 3
// baseline (speedup 1.0000x reference)
#include <cuda_runtime.h>
#include <cuda_fp16.h>

#define NN 100000
#define EE 3200000
#define FF 128
#define NB4 32          // float4 per fp32 row (128 floats)
#define NH2 32          // uint2 per fp16 row (128 halves = 256B = 32 uint2)
#define ITERS 50
#define FP32_TAIL 4     // last iterations in fp32 to squash fp16 bias
#define C1 0.5f
#define C2 0.5f

// ---------------- device-global scratch ----------------
__device__ __align__(16) __half g_h0[(size_t)NN * FF];
__device__ __align__(16) __half g_h1[(size_t)NN * FF];
__device__ __align__(16) float  g_f0[(size_t)NN * FF];
__device__ __align__(16) float  g_f1[(size_t)NN * FF];
__device__ __align__(16) float  g_xc[(size_t)NN * FF];
__device__ int   g_deg[NN];
__device__ float g_invdeg[NN];
__device__ int   g_rowptr[NN + 1];
__device__ int   g_cursor[NN];
__device__ int   g_col[EE];
__device__ float g_colsum[FF];
__device__ int   g_partials[128];
__device__ int   g_flag64;

// ---------------- dtype detection: int64 vs int32 edge_index ----------------
__global__ void k_detect(const int* __restrict__ ei32) {
    int t = threadIdx.x;
    int w = ei32[2 * t + 1];
    unsigned bal = __ballot_sync(0xffffffffu, w != 0);
    if (t == 0) g_flag64 = (bal == 0u) ? 1 : 0;
}

__global__ void k_zero() {
    int i = blockIdx.x * blockDim.x + threadIdx.x;
    if (i < NN) g_deg[i] = 0;
    if (i < FF) g_colsum[i] = 0.0f;
}

#define ROWS_PER_BLK 256
__global__ void k_colsum(const float* __restrict__ x) {
    int c  = threadIdx.x;
    int r0 = blockIdx.x * ROWS_PER_BLK;
    int r1 = r0 + ROWS_PER_BLK; if (r1 > NN) r1 = NN;
    float s = 0.0f;
    for (int r = r0; r < r1; r++) s += x[(size_t)r * FF + c];
    atomicAdd(&g_colsum[c], s);
}

__global__ void k_degree(const void* __restrict__ ei) {
    int e = blockIdx.x * blockDim.x + threadIdx.x;
    if (e >= EE) return;
    int r;
    if (g_flag64) r = (int)((const long long*)ei)[e];
    else          r = ((const int*)ei)[e];
    atomicAdd(&g_deg[r], 1);
}

__global__ void k_scan1() {
    __shared__ int s[1024];
    int i = blockIdx.x * 1024 + threadIdx.x;
    int v = (i < NN) ? g_deg[i] : 0;
    s[threadIdx.x] = v;
    __syncthreads();
    for (int off = 1; off < 1024; off <<= 1) {
        int t = (threadIdx.x >= off) ? s[threadIdx.x - off] : 0;
        __syncthreads();
        s[threadIdx.x] += t;
        __syncthreads();
    }
    if (i < NN) g_rowptr[i] = s[threadIdx.x] - v;
    if (threadIdx.x == 1023) g_partials[blockIdx.x] = s[1023];
}

__global__ void k_scan2() {
    if (threadIdx.x == 0) {
        int run = 0;
        for (int b = 0; b < 98; b++) { int t = g_partials[b]; g_partials[b] = run; run += t; }
        g_rowptr[NN] = run;
    }
}

__global__ void k_scan3() {
    int i = blockIdx.x * blockDim.x + threadIdx.x;
    if (i >= NN) return;
    int rp = g_rowptr[i] + g_partials[i >> 10];
    g_rowptr[i] = rp;
    g_cursor[i] = rp;
    g_invdeg[i] = 1.0f / (float)(g_deg[i] + 1);
}

__global__ void k_scatter(const void* __restrict__ ei) {
    int e = blockIdx.x * blockDim.x + threadIdx.x;
    if (e >= EE) return;
    int r, c;
    if (g_flag64) {
        const long long* p = (const long long*)ei;
        r = (int)p[e]; c = (int)p[(size_t)EE + e];
    } else {
        const int* p = (const int*)ei;
        r = p[e]; c = p[(size_t)EE + e];
    }
    int pos = atomicAdd(&g_cursor[r], 1);
    g_col[pos] = c;
}

__global__ void k_center(const float* __restrict__ x) {
    int i = blockIdx.x * blockDim.x + threadIdx.x;
    if (i >= NN * FF) return;
    float m = g_colsum[i & (FF - 1)] * (1.0f / (float)NN);
    float v = x[i] - m;
    g_xc[i] = v;
    g_h0[i] = __float2half_rn(v);
}

// ---------------- propagate kernels: warp per node ----------------
__device__ __forceinline__ void acc4h(float4& acc, uint2 r) {
    float2 fa = __half22float2(*(__half2*)&r.x);
    float2 fb = __half22float2(*(__half2*)&r.y);
    acc.x += fa.x; acc.y += fa.y; acc.z += fb.x; acc.w += fb.y;
}

// fp16 -> fp16 (OUT16=1) or fp16 -> fp32 (OUT16=0, transition iteration)
template <int OUT16>
__global__ void __launch_bounds__(256) k_prop_h(const uint2* __restrict__ cur,
                                                uint2* __restrict__ outh,
                                                float4* __restrict__ outf) {
    int gt   = blockIdx.x * blockDim.x + threadIdx.x;
    int node = gt >> 5;
    int lane = gt & 31;
    if (node >= NN) return;

    float4 acc = make_float4(0.f, 0.f, 0.f, 0.f);
    acc4h(acc, __ldg(&cur[(size_t)node * NH2 + lane]));   // self loop

    int k   = g_rowptr[node];
    int end = g_rowptr[node + 1];
    for (; k + 8 <= end; k += 8) {
        int j0 = __ldg(&g_col[k]);
        int j1 = __ldg(&g_col[k + 1]);
        int j2 = __ldg(&g_col[k + 2]);
        int j3 = __ldg(&g_col[k + 3]);
        int j4 = __ldg(&g_col[k + 4]);
        int j5 = __ldg(&g_col[k + 5]);
        int j6 = __ldg(&g_col[k + 6]);
        int j7 = __ldg(&g_col[k + 7]);
        uint2 r0 = __ldg(&cur[(size_t)j0 * NH2 + lane]);
        uint2 r1 = __ldg(&cur[(size_t)j1 * NH2 + lane]);
        uint2 r2 = __ldg(&cur[(size_t)j2 * NH2 + lane]);
        uint2 r3 = __ldg(&cur[(size_t)j3 * NH2 + lane]);
        uint2 r4 = __ldg(&cur[(size_t)j4 * NH2 + lane]);
        uint2 r5 = __ldg(&cur[(size_t)j5 * NH2 + lane]);
        uint2 r6 = __ldg(&cur[(size_t)j6 * NH2 + lane]);
        uint2 r7 = __ldg(&cur[(size_t)j7 * NH2 + lane]);
        acc4h(acc, r0); acc4h(acc, r1); acc4h(acc, r2); acc4h(acc, r3);
        acc4h(acc, r4); acc4h(acc, r5); acc4h(acc, r6); acc4h(acc, r7);
    }
    for (; k < end; k++) {
        int j = __ldg(&g_col[k]);
        acc4h(acc, __ldg(&cur[(size_t)j * NH2 + lane]));
    }

    float s = C1 * g_invdeg[node];
    float4 xcv = __ldg(&((const float4*)g_xc)[(size_t)node * NB4 + lane]);
    float4 o;
    o.x = fmaf(s, acc.x, C2 * xcv.x);
    o.y = fmaf(s, acc.y, C2 * xcv.y);
    o.z = fmaf(s, acc.z, C2 * xcv.z);
    o.w = fmaf(s, acc.w, C2 * xcv.w);

    if (OUT16) {
        uint2 p;
        *(__half2*)&p.x = __floats2half2_rn(o.x, o.y);
        *(__half2*)&p.y = __floats2half2_rn(o.z, o.w);
        outh[(size_t)node * NH2 + lane] = p;
    } else {
        outf[(size_t)node * NB4 + lane] = o;
    }
}

// fp32 -> fp32
__global__ void __launch_bounds__(256) k_prop_f(const float4* __restrict__ cur,
                                                float4* __restrict__ out) {
    int gt   = blockIdx.x * blockDim.x + threadIdx.x;
    int node = gt >> 5;
    int lane = gt & 31;
    if (node >= NN) return;

    float4 acc = __ldg(&cur[(size_t)node * NB4 + lane]);   // self loop

    int k   = g_rowptr[node];
    int end = g_rowptr[node + 1];
    for (; k + 4 <= end; k += 4) {
        int j0 = __ldg(&g_col[k]);
        int j1 = __ldg(&g_col[k + 1]);
        int j2 = __ldg(&g_col[k + 2]);
        int j3 = __ldg(&g_col[k + 3]);
        float4 a = __ldg(&cur[(size_t)j0 * NB4 + lane]);
        float4 b = __ldg(&cur[(size_t)j1 * NB4 + lane]);
        float4 c = __ldg(&cur[(size_t)j2 * NB4 + lane]);
        float4 d = __ldg(&cur[(size_t)j3 * NB4 + lane]);
        acc.x += a.x + b.x + c.x + d.x;
        acc.y += a.y + b.y + c.y + d.y;
        acc.z += a.z + b.z + c.z + d.z;
        acc.w += a.w + b.w + c.w + d.w;
    }
    for (; k < end; k++) {
        int j = __ldg(&g_col[k]);
        float4 a = __ldg(&cur[(size_t)j * NB4 + lane]);
        acc.x += a.x; acc.y += a.y; acc.z += a.z; acc.w += a.w;
    }

    float s = C1 * g_invdeg[node];
    float4 xcv = __ldg(&((const float4*)g_xc)[(size_t)node * NB4 + lane]);
    float4 o;
    o.x = fmaf(s, acc.x, C2 * xcv.x);
    o.y = fmaf(s, acc.y, C2 * xcv.y);
    o.z = fmaf(s, acc.z, C2 * xcv.z);
    o.w = fmaf(s, acc.w, C2 * xcv.w);
    out[(size_t)node * NB4 + lane] = o;
}

// ---------------- final GEMM: out = V @ W + bias ----------------
#define GEMM_SMEM ((FF * FF + 64 * 129) * (int)sizeof(float))
__global__ void __launch_bounds__(256) k_gemm(const float* __restrict__ V,
                                              const float* __restrict__ W,
                                              const float* __restrict__ bias,
                                              float* __restrict__ out) {
    extern __shared__ float sh[];
    float* Ws = sh;
    float* Vs = sh + FF * FF;

    int tid = threadIdx.x;
    for (int i = tid; i < FF * FF; i += 256) Ws[i] = W[i];

    int n0 = blockIdx.x * 64;
    for (int l = tid; l < 64 * FF; l += 256) {
        int nl = l >> 7, kk = l & 127;
        int n = n0 + nl;
        Vs[nl * 129 + kk] = (n < NN) ? V[(size_t)n * FF + kk] : 0.0f;
    }
    __syncthreads();

    int nl   = tid & 63;
    int quad = tid >> 6;
    float4 acc[8];
#pragma unroll
    for (int c = 0; c < 8; c++) acc[c] = make_float4(0.f, 0.f, 0.f, 0.f);

    const float* vp = &Vs[nl * 129];
#pragma unroll 4
    for (int kk = 0; kk < FF; kk++) {
        float vk = vp[kk];
        const float4* wr = (const float4*)&Ws[kk * FF + quad * 32];
#pragma unroll
        for (int c = 0; c < 8; c++) {
            float4 w4 = wr[c];
            acc[c].x += vk * w4.x;
            acc[c].y += vk * w4.y;
            acc[c].z += vk * w4.z;
            acc[c].w += vk * w4.w;
        }
    }

    int n = n0 + nl;
    if (n < NN) {
        const float4* b4 = (const float4*)&bias[quad * 32];
        float4* o4 = (float4*)&out[(size_t)n * FF + quad * 32];
#pragma unroll
        for (int c = 0; c < 8; c++) {
            float4 bb = __ldg(&b4[c]);
            o4[c] = make_float4(acc[c].x + bb.x, acc[c].y + bb.y,
                                acc[c].z + bb.z, acc[c].w + bb.w);
        }
    }
}

extern "C" void kernel_launch(void* const* d_in, const int* in_sizes, int n_in,
                              void* d_out, int out_size) {
    const float* x    = (const float*)d_in[0];
    const void*  ei   = d_in[1];
    const float* W    = (const float*)d_in[2];
    const float* bias = (const float*)d_in[3];
    float* out = (float*)d_out;

    cudaFuncSetAttribute(k_gemm, cudaFuncAttributeMaxDynamicSharedMemorySize, GEMM_SMEM);

    k_detect<<<1, 32>>>((const int*)ei);
    k_zero<<<(NN + 255) / 256, 256>>>();
    k_colsum<<<(NN + ROWS_PER_BLK - 1) / ROWS_PER_BLK, FF>>>(x);
    k_degree<<<(EE + 255) / 256, 256>>>(ei);
    k_scan1<<<(NN + 1023) / 1024, 1024>>>();
    k_scan2<<<1, 32>>>();
    k_scan3<<<(NN + 255) / 256, 256>>>();
    k_scatter<<<(EE + 255) / 256, 256>>>(ei);
    k_center<<<(NN * FF + 255) / 256, 256>>>(x);

    uint2*  h0 = (uint2*)g_h0;
    uint2*  h1 = (uint2*)g_h1;
    float4* f0 = (float4*)g_f0;
    float4* f1 = (float4*)g_f1;
    int grid = (NN * 32 + 255) / 256;

    // iterations 0 .. 50-FP32_TAIL-2 : fp16 -> fp16 ping-pong
    const int n_h = ITERS - FP32_TAIL - 1;   // 45 pure-fp16 iterations (0..44)
    for (int it = 0; it < n_h; it++) {
        if (it & 1) k_prop_h<1><<<grid, 256>>>(h1, h0, nullptr);
        else        k_prop_h<1><<<grid, 256>>>(h0, h1, nullptr);
    }
    // transition iteration (it = n_h): fp16 -> fp32
    const uint2* hin = (n_h & 1) ? h1 : h0;
    k_prop_h<0><<<grid, 256>>>(hin, nullptr, f0);
    // fp32 tail: FP32_TAIL iterations total includes nothing extra —
    // transition was iteration n_h; remaining ITERS-1-n_h = FP32_TAIL fp32 iters
    float4* cur = f0; float4* nxt = f1;
    for (int it = n_h + 1; it < ITERS; it++) {
        k_prop_f<<<grid, 256>>>(cur, nxt);
        float4* t = cur; cur = nxt; nxt = t;
    }
    // final iterate is in `cur`
    k_gemm<<<(NN + 63) / 64, 256, GEMM_SMEM>>>((const float*)cur, W, bias, out);
}

// round 4
// speedup vs baseline: 75.1632x; 75.1632x over previous
#include <cuda_runtime.h>
#include <cuda_fp16.h>

#define NN 100000
#define EE 3200000
#define FF 128
#define NB4 32          // float4 per fp32 row
#define NH2 32          // uint2 per fp16 row (128 halves = 256B)
#define ITERS 50
#define C1 0.5f
#define C2 0.5f

// ---------------- device-global scratch ----------------
__device__ __align__(16) __half g_h0[(size_t)NN * FF];
__device__ __align__(16) __half g_h1[(size_t)NN * FF];
__device__ __align__(16) float  g_f0[(size_t)NN * FF];
__device__ __align__(16) float  g_f1[(size_t)NN * FF];
__device__ __align__(16) float  g_xc[(size_t)NN * FF];
__device__ int   g_deg[NN];
__device__ float g_invdeg[NN];
__device__ int   g_rowptr[NN + 1];
__device__ int   g_cursor[NN];
__device__ int   g_col[EE];
__device__ float g_colsum[FF];
__device__ int   g_partials[128];
__device__ int   g_flag64;

// ---------------- dtype detection: int64 vs int32 edge_index ----------------
__global__ void k_detect(const int* __restrict__ ei32) {
    int t = threadIdx.x;
    int w = ei32[2 * t + 1];
    unsigned bal = __ballot_sync(0xffffffffu, w != 0);
    if (t == 0) g_flag64 = (bal == 0u) ? 1 : 0;
}

__global__ void k_zero() {
    int i = blockIdx.x * blockDim.x + threadIdx.x;
    if (i < NN) g_deg[i] = 0;
    if (i < FF) g_colsum[i] = 0.0f;
}

#define ROWS_PER_BLK 256
__global__ void k_colsum(const float* __restrict__ x) {
    int c  = threadIdx.x;
    int r0 = blockIdx.x * ROWS_PER_BLK;
    int r1 = r0 + ROWS_PER_BLK; if (r1 > NN) r1 = NN;
    float s = 0.0f;
    for (int r = r0; r < r1; r++) s += x[(size_t)r * FF + c];
    atomicAdd(&g_colsum[c], s);
}

__global__ void k_degree(const void* __restrict__ ei) {
    int e = blockIdx.x * blockDim.x + threadIdx.x;
    if (e >= EE) return;
    int r;
    if (g_flag64) r = (int)((const long long*)ei)[e];
    else          r = ((const int*)ei)[e];
    atomicAdd(&g_deg[r], 1);
}

__global__ void k_scan1() {
    __shared__ int s[1024];
    int i = blockIdx.x * 1024 + threadIdx.x;
    int v = (i < NN) ? g_deg[i] : 0;
    s[threadIdx.x] = v;
    __syncthreads();
    for (int off = 1; off < 1024; off <<= 1) {
        int t = (threadIdx.x >= off) ? s[threadIdx.x - off] : 0;
        __syncthreads();
        s[threadIdx.x] += t;
        __syncthreads();
    }
    if (i < NN) g_rowptr[i] = s[threadIdx.x] - v;
    if (threadIdx.x == 1023) g_partials[blockIdx.x] = s[1023];
}

__global__ void k_scan2() {
    if (threadIdx.x == 0) {
        int run = 0;
        for (int b = 0; b < 98; b++) { int t = g_partials[b]; g_partials[b] = run; run += t; }
        g_rowptr[NN] = run;
    }
}

__global__ void k_scan3() {
    int i = blockIdx.x * blockDim.x + threadIdx.x;
    if (i >= NN) return;
    int rp = g_rowptr[i] + g_partials[i >> 10];
    g_rowptr[i] = rp;
    g_cursor[i] = rp;
    g_invdeg[i] = 1.0f / (float)(g_deg[i] + 1);
}

__global__ void k_scatter(const void* __restrict__ ei) {
    int e = blockIdx.x * blockDim.x + threadIdx.x;
    if (e >= EE) return;
    int r, c;
    if (g_flag64) {
        const long long* p = (const long long*)ei;
        r = (int)p[e]; c = (int)p[(size_t)EE + e];
    } else {
        const int* p = (const int*)ei;
        r = p[e]; c = p[(size_t)EE + e];
    }
    int pos = atomicAdd(&g_cursor[r], 1);
    g_col[pos] = c;
}

__global__ void k_center(const float* __restrict__ x) {
    int i = blockIdx.x * blockDim.x + threadIdx.x;
    if (i >= NN * FF) return;
    float m = g_colsum[i & (FF - 1)] * (1.0f / (float)NN);
    float v = x[i] - m;
    g_xc[i] = v;
    g_h0[i] = __float2half_rn(v);
}

// ---------------- propagate: warp per node, buffers selected at COMPILE time ----------------
__device__ __forceinline__ void acc4h(float4& acc, uint2 r) {
    float2 fa = __half22float2(*(__half2*)&r.x);
    float2 fb = __half22float2(*(__half2*)&r.y);
    acc.x += fa.x; acc.y += fa.y; acc.z += fb.x; acc.w += fb.y;
}

// SRC: 0 = read g_h0, 1 = read g_h1.  OUT16: 1 = write other fp16 buf, 0 = write g_f0 (fp32)
template <int SRC, int OUT16>
__global__ void __launch_bounds__(256) k_prop_h() {
    const uint2* __restrict__ cur = (const uint2*)(SRC ? g_h1 : g_h0);
    uint2*       __restrict__ outh = (uint2*)(SRC ? g_h0 : g_h1);

    int gt   = blockIdx.x * blockDim.x + threadIdx.x;
    int node = gt >> 5;
    int lane = gt & 31;
    if (node >= NN) return;

    float4 acc = make_float4(0.f, 0.f, 0.f, 0.f);
    acc4h(acc, __ldg(&cur[(size_t)node * NH2 + lane]));   // self loop

    int k   = g_rowptr[node];
    int end = g_rowptr[node + 1];
    for (; k + 8 <= end; k += 8) {
        int j0 = __ldg(&g_col[k]);
        int j1 = __ldg(&g_col[k + 1]);
        int j2 = __ldg(&g_col[k + 2]);
        int j3 = __ldg(&g_col[k + 3]);
        int j4 = __ldg(&g_col[k + 4]);
        int j5 = __ldg(&g_col[k + 5]);
        int j6 = __ldg(&g_col[k + 6]);
        int j7 = __ldg(&g_col[k + 7]);
        uint2 r0 = __ldg(&cur[(size_t)j0 * NH2 + lane]);
        uint2 r1 = __ldg(&cur[(size_t)j1 * NH2 + lane]);
        uint2 r2 = __ldg(&cur[(size_t)j2 * NH2 + lane]);
        uint2 r3 = __ldg(&cur[(size_t)j3 * NH2 + lane]);
        uint2 r4 = __ldg(&cur[(size_t)j4 * NH2 + lane]);
        uint2 r5 = __ldg(&cur[(size_t)j5 * NH2 + lane]);
        uint2 r6 = __ldg(&cur[(size_t)j6 * NH2 + lane]);
        uint2 r7 = __ldg(&cur[(size_t)j7 * NH2 + lane]);
        acc4h(acc, r0); acc4h(acc, r1); acc4h(acc, r2); acc4h(acc, r3);
        acc4h(acc, r4); acc4h(acc, r5); acc4h(acc, r6); acc4h(acc, r7);
    }
    for (; k < end; k++) {
        int j = __ldg(&g_col[k]);
        acc4h(acc, __ldg(&cur[(size_t)j * NH2 + lane]));
    }

    float s = C1 * g_invdeg[node];
    float4 xcv = __ldg(&((const float4*)g_xc)[(size_t)node * NB4 + lane]);
    float4 o;
    o.x = fmaf(s, acc.x, C2 * xcv.x);
    o.y = fmaf(s, acc.y, C2 * xcv.y);
    o.z = fmaf(s, acc.z, C2 * xcv.z);
    o.w = fmaf(s, acc.w, C2 * xcv.w);

    if (OUT16) {
        uint2 p;
        *(__half2*)&p.x = __floats2half2_rn(o.x, o.y);
        *(__half2*)&p.y = __floats2half2_rn(o.z, o.w);
        outh[(size_t)node * NH2 + lane] = p;
    } else {
        ((float4*)g_f0)[(size_t)node * NB4 + lane] = o;
    }
}

// fp32 -> fp32. SRC: 0 = read g_f0 write g_f1; 1 = read g_f1 write g_f0
template <int SRC>
__global__ void __launch_bounds__(256) k_prop_f() {
    const float4* __restrict__ cur = (const float4*)(SRC ? g_f1 : g_f0);
    float4*       __restrict__ out = (float4*)(SRC ? g_f0 : g_f1);

    int gt   = blockIdx.x * blockDim.x + threadIdx.x;
    int node = gt >> 5;
    int lane = gt & 31;
    if (node >= NN) return;

    float4 acc = __ldg(&cur[(size_t)node * NB4 + lane]);   // self loop

    int k   = g_rowptr[node];
    int end = g_rowptr[node + 1];
    for (; k + 4 <= end; k += 4) {
        int j0 = __ldg(&g_col[k]);
        int j1 = __ldg(&g_col[k + 1]);
        int j2 = __ldg(&g_col[k + 2]);
        int j3 = __ldg(&g_col[k + 3]);
        float4 a = __ldg(&cur[(size_t)j0 * NB4 + lane]);
        float4 b = __ldg(&cur[(size_t)j1 * NB4 + lane]);
        float4 c = __ldg(&cur[(size_t)j2 * NB4 + lane]);
        float4 d = __ldg(&cur[(size_t)j3 * NB4 + lane]);
        acc.x += a.x + b.x + c.x + d.x;
        acc.y += a.y + b.y + c.y + d.y;
        acc.z += a.z + b.z + c.z + d.z;
        acc.w += a.w + b.w + c.w + d.w;
    }
    for (; k < end; k++) {
        int j = __ldg(&g_col[k]);
        float4 a = __ldg(&cur[(size_t)j * NB4 + lane]);
        acc.x += a.x; acc.y += a.y; acc.z += a.z; acc.w += a.w;
    }

    float s = C1 * g_invdeg[node];
    float4 xcv = __ldg(&((const float4*)g_xc)[(size_t)node * NB4 + lane]);
    float4 o;
    o.x = fmaf(s, acc.x, C2 * xcv.x);
    o.y = fmaf(s, acc.y, C2 * xcv.y);
    o.z = fmaf(s, acc.z, C2 * xcv.z);
    o.w = fmaf(s, acc.w, C2 * xcv.w);
    out[(size_t)node * NB4 + lane] = o;
}

// ---------------- final GEMM: out = g_f0 @ W + bias ----------------
#define GEMM_SMEM ((FF * FF + 64 * 129) * (int)sizeof(float))
__global__ void __launch_bounds__(256) k_gemm(const float* __restrict__ W,
                                              const float* __restrict__ bias,
                                              float* __restrict__ out) {
    extern __shared__ float sh[];
    float* Ws = sh;
    float* Vs = sh + FF * FF;

    int tid = threadIdx.x;
    for (int i = tid; i < FF * FF; i += 256) Ws[i] = W[i];

    int n0 = blockIdx.x * 64;
    for (int l = tid; l < 64 * FF; l += 256) {
        int nl = l >> 7, kk = l & 127;
        int n = n0 + nl;
        Vs[nl * 129 + kk] = (n < NN) ? g_f0[(size_t)n * FF + kk] : 0.0f;
    }
    __syncthreads();

    int nl   = tid & 63;
    int quad = tid >> 6;
    float4 acc[8];
#pragma unroll
    for (int c = 0; c < 8; c++) acc[c] = make_float4(0.f, 0.f, 0.f, 0.f);

    const float* vp = &Vs[nl * 129];
#pragma unroll 4
    for (int kk = 0; kk < FF; kk++) {
        float vk = vp[kk];
        const float4* wr = (const float4*)&Ws[kk * FF + quad * 32];
#pragma unroll
        for (int c = 0; c < 8; c++) {
            float4 w4 = wr[c];
            acc[c].x += vk * w4.x;
            acc[c].y += vk * w4.y;
            acc[c].z += vk * w4.z;
            acc[c].w += vk * w4.w;
        }
    }

    int n = n0 + nl;
    if (n < NN) {
        const float4* b4 = (const float4*)&bias[quad * 32];
        float4* o4 = (float4*)&out[(size_t)n * FF + quad * 32];
#pragma unroll
        for (int c = 0; c < 8; c++) {
            float4 bb = __ldg(&b4[c]);
            o4[c] = make_float4(acc[c].x + bb.x, acc[c].y + bb.y,
                                acc[c].z + bb.z, acc[c].w + bb.w);
        }
    }
}

extern "C" void kernel_launch(void* const* d_in, const int* in_sizes, int n_in,
                              void* d_out, int out_size) {
    const float* x    = (const float*)d_in[0];
    const void*  ei   = d_in[1];
    const float* W    = (const float*)d_in[2];
    const float* bias = (const float*)d_in[3];
    float* out = (float*)d_out;

    cudaFuncSetAttribute(k_gemm, cudaFuncAttributeMaxDynamicSharedMemorySize, GEMM_SMEM);

    k_detect<<<1, 32>>>((const int*)ei);
    k_zero<<<(NN + 255) / 256, 256>>>();
    k_colsum<<<(NN + ROWS_PER_BLK - 1) / ROWS_PER_BLK, FF>>>(x);
    k_degree<<<(EE + 255) / 256, 256>>>(ei);
    k_scan1<<<(NN + 1023) / 1024, 1024>>>();
    k_scan2<<<1, 32>>>();
    k_scan3<<<(NN + 255) / 256, 256>>>();
    k_scatter<<<(EE + 255) / 256, 256>>>(ei);
    k_center<<<(NN * FF + 255) / 256, 256>>>(x);

    const int grid = (NN * 32 + 255) / 256;

    // iterations 0..46: fp16 -> fp16 ping-pong (even reads h0, odd reads h1)
    for (int it = 0; it < 47; it++) {
        if (it & 1) k_prop_h<1, 1><<<grid, 256>>>();
        else        k_prop_h<0, 1><<<grid, 256>>>();
    }
    // iteration 47: fp16 (h1, since 47 is odd) -> fp32 g_f0
    k_prop_h<1, 0><<<grid, 256>>>();
    // iterations 48, 49: fp32 tail; final lands in g_f0
    k_prop_f<0><<<grid, 256>>>();   // f0 -> f1
    k_prop_f<1><<<grid, 256>>>();   // f1 -> f0

    k_gemm<<<(NN + 63) / 64, 256, GEMM_SMEM>>>(W, bias, out);
}